// round 3
// baseline (speedup 1.0000x reference)
#include <cuda_runtime.h>
#include <cuda_bf16.h>

#define N_NODES_MAX 100000
#define N_GRAPHS 256
#define HID 64
#define N_TASKS 10

// ---------------- scratch (no allocations allowed) ----------------
__device__ __align__(16) float d_agg[N_NODES_MAX * HID];
__device__ __align__(16) float d_hA[N_NODES_MAX * HID];
__device__ __align__(16) float d_hB[N_NODES_MAX * HID];
__device__ __align__(16) float d_pooled[N_GRAPHS * HID];
__device__ __align__(16) float d_cnt[N_GRAPHS];
__device__ __align__(16) float d_Wf2[16 * HID];
__device__ __align__(16) float d_bf2[HID];

// ---------------- prep: fused edge weights Wf2 = We1@We2, bf2 = be1@We2 + be2 ----------------
__global__ void prep_kernel(const float* __restrict__ We1, const float* __restrict__ be1,
                            const float* __restrict__ We2, const float* __restrict__ be2,
                            float* __restrict__ Wf2, float* __restrict__ bf2) {
    int idx = blockIdx.x * blockDim.x + threadIdx.x;
    if (idx < 16 * HID) {
        int k = idx >> 6, j = idx & 63;
        float acc = 0.f;
        #pragma unroll 8
        for (int m = 0; m < HID; m++) acc += We1[k * HID + m] * We2[m * HID + j];
        Wf2[idx] = acc;
    } else if (idx < 16 * HID + HID) {
        int j = idx - 16 * HID;
        float acc = be2[j];
        #pragma unroll 8
        for (int m = 0; m < HID; m++) acc += be1[m] * We2[m * HID + j];
        bf2[j] = acc;
    }
}

// ---------------- zero fill ----------------
__global__ void zero_kernel(float4* __restrict__ p, int n4) {
    int i = blockIdx.x * blockDim.x + threadIdx.x;
    if (i < n4) p[i] = make_float4(0.f, 0.f, 0.f, 0.f);
}

// ---------------- edge phase: agg[dst] += relu(x[src] + edge_attr@W + b) ----------------
// 16 threads per edge; thread t owns output features [4t,4t+4); W slice lives in registers.
__global__ void __launch_bounds__(256) edge_kernel(
    const float* __restrict__ xin,
    const int* __restrict__ src,
    const int* __restrict__ dst,
    const float* __restrict__ ea,    // [E,16]
    const float* __restrict__ W,     // [16,64]
    const float* __restrict__ b,     // [64]
    float* __restrict__ agg,
    int nE)
{
    const int tid = threadIdx.x;
    const int t = tid & 15;            // sub-thread within edge group
    const int g = tid >> 4;            // edge slot within block (0..15)
    const unsigned shfl_base = (tid & 31) & 16;

    // register-resident W column slice: W[k][4t..4t+3]
    float4 w[16];
    #pragma unroll
    for (int k = 0; k < 16; k++) w[k] = *(const float4*)(W + k * HID + 4 * t);
    const float4 bv = *(const float4*)(b + 4 * t);

    for (int base = blockIdx.x * 16; base < nE; base += gridDim.x * 16) {
        int e = base + g;
        bool valid = (e < nE);
        int ec = valid ? e : (nE - 1);

        float eav = ea[(long long)ec * 16 + t];   // coalesced: 16 contiguous rows per block
        int s = src[ec];
        int d = dst[ec];

        float a0 = bv.x, a1 = bv.y, a2 = bv.z, a3 = bv.w;
        #pragma unroll
        for (int k = 0; k < 16; k++) {
            float av = __shfl_sync(0xffffffffu, eav, shfl_base + k);
            a0 += av * w[k].x;
            a1 += av * w[k].y;
            a2 += av * w[k].z;
            a3 += av * w[k].w;
        }

        float4 xv = *(const float4*)(xin + (long long)s * HID + 4 * t);
        float4 m;
        m.x = fmaxf(xv.x + a0, 0.f);
        m.y = fmaxf(xv.y + a1, 0.f);
        m.z = fmaxf(xv.z + a2, 0.f);
        m.w = fmaxf(xv.w + a3, 0.f);

        if (valid)
            atomicAdd((float4*)(agg + (long long)d * HID + 4 * t), m);  // vector RED
    }
}

// ---------------- node phase: out = act(((1+eps)*x + agg) @ W + b) ----------------
template <bool RELU>
__global__ void __launch_bounds__(256) node_kernel(
    const float* __restrict__ xin,
    const float* __restrict__ agg,
    const float* __restrict__ W,     // [64,64]
    const float* __restrict__ b,
    const float* __restrict__ epsp,
    float* __restrict__ out,
    int nN)
{
    __shared__ float srow[4][HID];
    const int j = threadIdx.x & 63;
    const int slot = threadIdx.x >> 6;
    const float scale = 1.f + epsp[0];

    float wc[HID];
    #pragma unroll
    for (int k = 0; k < HID; k++) wc[k] = W[k * HID + j];  // coalesced per k
    const float bj = b[j];

    for (int base = blockIdx.x * 4; base < nN; base += gridDim.x * 4) {
        int n = base + slot;
        if (n < nN)
            srow[slot][j] = scale * xin[(long long)n * HID + j] + agg[(long long)n * HID + j];
        __syncthreads();
        if (n < nN) {
            float acc = bj;
            #pragma unroll
            for (int k = 0; k < HID; k += 4) {
                float4 r = *(const float4*)&srow[slot][k];   // broadcast LDS.128
                acc += r.x * wc[k] + r.y * wc[k + 1] + r.z * wc[k + 2] + r.w * wc[k + 3];
            }
            out[(long long)n * HID + j] = RELU ? fmaxf(acc, 0.f) : acc;
        }
        __syncthreads();
    }
}

// ---------------- pooling: scatter-mean over sorted batch ----------------
__global__ void pool_kernel(const float* __restrict__ h,
                            const int* __restrict__ batch,
                            float* __restrict__ pooled,
                            float* __restrict__ cnt,
                            int nN)
{
    const int j = threadIdx.x & 63;
    const int p = threadIdx.x >> 6;
    const int CHUNK = 512;
    int base = blockIdx.x * CHUNK;
    int lim = base + CHUNK;
    if (lim > nN) lim = nN;

    float acc = 0.f;
    float c = 0.f;
    int curg = -1;
    for (int n = base + p; n < lim; n += 4) {
        int g = batch[n];
        if (g != curg) {
            if (curg >= 0) {
                atomicAdd(&pooled[curg * HID + j], acc);
                if (j == 0) atomicAdd(&cnt[curg], c);
            }
            acc = 0.f; c = 0.f; curg = g;
        }
        acc += h[(long long)n * HID + j];
        c += 1.f;
    }
    if (curg >= 0) {
        atomicAdd(&pooled[curg * HID + j], acc);
        if (j == 0) atomicAdd(&cnt[curg], c);
    }
}

// ---------------- head: out = relu(pooled/cnt @ Wm1 + bm1) @ Wm2 + bm2 ----------------
__global__ void head_kernel(const float* __restrict__ pooled,
                            const float* __restrict__ cnt,
                            const float* __restrict__ Wm1, const float* __restrict__ bm1,
                            const float* __restrict__ Wm2, const float* __restrict__ bm2,
                            float* __restrict__ out)
{
    int gq = blockIdx.x * blockDim.x + threadIdx.x;
    if (gq >= N_GRAPHS) return;
    float inv = 1.f / fmaxf(cnt[gq], 1.f);
    float row[HID];
    #pragma unroll
    for (int k = 0; k < HID; k++) row[k] = pooled[gq * HID + k] * inv;
    float o[N_TASKS];
    #pragma unroll
    for (int ts = 0; ts < N_TASKS; ts++) o[ts] = bm2[ts];
    for (int jj = 0; jj < HID; jj++) {
        float hv = bm1[jj];
        #pragma unroll 16
        for (int k = 0; k < HID; k++) hv += row[k] * Wm1[k * HID + jj];  // broadcast LDG
        hv = fmaxf(hv, 0.f);
        #pragma unroll
        for (int ts = 0; ts < N_TASKS; ts++) o[ts] += hv * Wm2[jj * N_TASKS + ts];
    }
    #pragma unroll
    for (int ts = 0; ts < N_TASKS; ts++) out[gq * N_TASKS + ts] = o[ts];
}

// ---------------- launch ----------------
extern "C" void kernel_launch(void* const* d_in, const int* in_sizes, int n_in,
                              void* d_out, int out_size) {
    const float* x         = (const float*)d_in[0];
    const int*   eidx      = (const int*)d_in[1];      // int64 in reference -> delivered int32
    const float* edge_attr = (const float*)d_in[2];
    const int*   batch     = (const int*)d_in[3];
    const float* We1 = (const float*)d_in[4];
    const float* be1 = (const float*)d_in[5];
    const float* We2 = (const float*)d_in[6];
    const float* be2 = (const float*)d_in[7];
    const float* W1  = (const float*)d_in[8];
    const float* b1  = (const float*)d_in[9];
    const float* e1  = (const float*)d_in[10];
    const float* W2  = (const float*)d_in[11];
    const float* b2  = (const float*)d_in[12];
    const float* e2  = (const float*)d_in[13];
    const float* W3  = (const float*)d_in[14];
    const float* b3  = (const float*)d_in[15];
    const float* e3  = (const float*)d_in[16];
    const float* Wm1 = (const float*)d_in[17];
    const float* bm1 = (const float*)d_in[18];
    const float* Wm2 = (const float*)d_in[19];
    const float* bm2 = (const float*)d_in[20];
    float* out = (float*)d_out;

    int nN = in_sizes[0] / HID;       // 100000
    int nE = in_sizes[2] / 16;        // 1600000
    const int* src = eidx;
    const int* dst = eidx + nE;

    float *agg, *hA, *hB, *pooled, *cnt, *Wf2, *bf2;
    cudaGetSymbolAddress((void**)&agg,    d_agg);
    cudaGetSymbolAddress((void**)&hA,     d_hA);
    cudaGetSymbolAddress((void**)&hB,     d_hB);
    cudaGetSymbolAddress((void**)&pooled, d_pooled);
    cudaGetSymbolAddress((void**)&cnt,    d_cnt);
    cudaGetSymbolAddress((void**)&Wf2,    d_Wf2);
    cudaGetSymbolAddress((void**)&bf2,    d_bf2);

    const int nodeF4 = nN * HID / 4;
    const int ZB = 256;
    const int edgeGrid = 4096;
    const int nodeGrid = 2048;

    prep_kernel<<<(16 * HID + HID + 127) / 128, 128>>>(We1, be1, We2, be2, Wf2, bf2);

    // conv1 (edge transform uses raw We1/be1)
    zero_kernel<<<(nodeF4 + ZB - 1) / ZB, ZB>>>((float4*)agg, nodeF4);
    edge_kernel<<<edgeGrid, 256>>>(x, src, dst, edge_attr, We1, be1, agg, nE);
    node_kernel<true><<<nodeGrid, 256>>>(x, agg, W1, b1, e1, hA, nN);

    // conv2 (edge transform uses fused Wf2/bf2)
    zero_kernel<<<(nodeF4 + ZB - 1) / ZB, ZB>>>((float4*)agg, nodeF4);
    edge_kernel<<<edgeGrid, 256>>>(hA, src, dst, edge_attr, Wf2, bf2, agg, nE);
    node_kernel<true><<<nodeGrid, 256>>>(hA, agg, W2, b2, e2, hB, nN);

    // conv3 (no relu)
    zero_kernel<<<(nodeF4 + ZB - 1) / ZB, ZB>>>((float4*)agg, nodeF4);
    edge_kernel<<<edgeGrid, 256>>>(hB, src, dst, edge_attr, Wf2, bf2, agg, nE);
    node_kernel<false><<<nodeGrid, 256>>>(hB, agg, W3, b3, e3, hA, nN);

    // pooling + head
    zero_kernel<<<(N_GRAPHS * HID / 4 + ZB - 1) / ZB, ZB>>>((float4*)pooled, N_GRAPHS * HID / 4);
    zero_kernel<<<1, ZB>>>((float4*)cnt, N_GRAPHS / 4);
    pool_kernel<<<(nN + 511) / 512, 256>>>(hA, batch, pooled, cnt, nN);
    head_kernel<<<1, 256>>>(pooled, cnt, Wm1, bm1, Wm2, bm2, out);
}

// round 4
// speedup vs baseline: 1.0736x; 1.0736x over previous
#include <cuda_runtime.h>
#include <cuda_bf16.h>

#define N_NODES_MAX 100000
#define NE_MAX 1600000
#define N_GRAPHS 256
#define HID 64
#define N_TASKS 10

// ---------------- scratch (no allocations allowed) ----------------
__device__ __align__(16) float d_agg[N_NODES_MAX * HID];
__device__ __align__(16) float d_hA[N_NODES_MAX * HID];
__device__ __align__(16) float d_hB[N_NODES_MAX * HID];
__device__ __align__(16) float d_pooled[N_GRAPHS * HID];
__device__ __align__(16) float d_cnt[N_GRAPHS];
__device__ __align__(16) float d_Wf2[16 * HID];
__device__ __align__(16) float d_bf2[HID];
// CSR scratch
__device__ int d_hist[N_NODES_MAX];
__device__ int d_cur[N_NODES_MAX];
__device__ int d_offs[N_NODES_MAX + 1];
__device__ int d_eid[NE_MAX];
__device__ int d_srcs[NE_MAX];

// ---------------- prep: fused edge weights Wf2 = We1@We2, bf2 = be1@We2 + be2 ----------------
__global__ void prep_kernel(const float* __restrict__ We1, const float* __restrict__ be1,
                            const float* __restrict__ We2, const float* __restrict__ be2,
                            float* __restrict__ Wf2, float* __restrict__ bf2) {
    int idx = blockIdx.x * blockDim.x + threadIdx.x;
    if (idx < 16 * HID) {
        int k = idx >> 6, j = idx & 63;
        float acc = 0.f;
        #pragma unroll 8
        for (int m = 0; m < HID; m++) acc += We1[k * HID + m] * We2[m * HID + j];
        Wf2[idx] = acc;
    } else if (idx < 16 * HID + HID) {
        int j = idx - 16 * HID;
        float acc = be2[j];
        #pragma unroll 8
        for (int m = 0; m < HID; m++) acc += be1[m] * We2[m * HID + j];
        bf2[j] = acc;
    }
}

// ---------------- zero fills ----------------
__global__ void zero_f4(float4* __restrict__ p, int n4) {
    int i = blockIdx.x * blockDim.x + threadIdx.x;
    if (i < n4) p[i] = make_float4(0.f, 0.f, 0.f, 0.f);
}
__global__ void zero_i(int* __restrict__ p, int n) {
    int i = blockIdx.x * blockDim.x + threadIdx.x;
    if (i < n) p[i] = 0;
}

// ---------------- CSR build ----------------
__global__ void hist_kernel(const int* __restrict__ dst, int* __restrict__ hist, int nE) {
    int e = blockIdx.x * blockDim.x + threadIdx.x;
    if (e < nE) atomicAdd(&hist[dst[e]], 1);
}

// single-block exclusive scan of hist[0..nN) -> offs[0..nN]
__global__ void scan_kernel(const int* __restrict__ hist, int* __restrict__ offs, int nN) {
    __shared__ int ssum[1024];
    const int tid = threadIdx.x;
    const int chunk = (nN + 1023) / 1024;
    int begin = tid * chunk;
    int end = begin + chunk; if (end > nN) end = nN;
    if (begin > nN) begin = nN;

    int s = 0;
    for (int i = begin; i < end; i++) s += hist[i];
    ssum[tid] = s;
    __syncthreads();
    // inclusive Hillis-Steele
    for (int off = 1; off < 1024; off <<= 1) {
        int add = (tid >= off) ? ssum[tid - off] : 0;
        __syncthreads();
        ssum[tid] += add;
        __syncthreads();
    }
    int run = (tid == 0) ? 0 : ssum[tid - 1];
    for (int i = begin; i < end; i++) { offs[i] = run; run += hist[i]; }
    if (tid == 1023) offs[nN] = ssum[1023];
}

__global__ void scatter_kernel(const int* __restrict__ src, const int* __restrict__ dst,
                               const int* __restrict__ offs, int* __restrict__ cur,
                               int* __restrict__ eid_s, int* __restrict__ src_s, int nE) {
    int e = blockIdx.x * blockDim.x + threadIdx.x;
    if (e < nE) {
        int d = dst[e];
        int p = atomicAdd(&cur[d], 1);
        int i = offs[d] + p;
        eid_s[i] = e;
        src_s[i] = src[e];
    }
}

// ---------------- edge phase (gather, no atomics) ----------------
// 16 threads per destination node; thread t owns output features [4t,4t+4).
// agg[n] = sum over incoming edges of relu(x[src] + ea@W + b)
__global__ void __launch_bounds__(128) edge_gather_kernel(
    const float* __restrict__ xin,
    const int* __restrict__ offs,
    const int* __restrict__ eid_s,
    const int* __restrict__ src_s,
    const float* __restrict__ ea,    // [E,16]
    const float* __restrict__ W,     // [16,64]
    const float* __restrict__ b,     // [64]
    float* __restrict__ agg,
    int nN)
{
    const int tid = threadIdx.x;
    const int t = tid & 15;
    const int slot = tid >> 4;                 // 0..7 nodes per block
    const unsigned shfl_base = (tid & 31) & 16;

    // register-resident W column slice: W[k][4t..4t+3]
    float4 w[16];
    #pragma unroll
    for (int k = 0; k < 16; k++) w[k] = *(const float4*)(W + k * HID + 4 * t);
    const float4 bv = *(const float4*)(b + 4 * t);

    int node = blockIdx.x * 8 + slot;
    if (node >= nN) return;

    int start = offs[node];
    int end = offs[node + 1];

    float4 acc = make_float4(0.f, 0.f, 0.f, 0.f);

    for (int i = start; i < end; i++) {
        int eid = eid_s[i];          // uniform within 16-thread group
        int s = src_s[i];

        float eav = ea[(long long)eid * 16 + t];   // 64B per edge across group

        float a0 = bv.x, a1 = bv.y, a2 = bv.z, a3 = bv.w;
        #pragma unroll
        for (int k = 0; k < 16; k++) {
            float av = __shfl_sync(0xffffffffu, eav, shfl_base + k);
            a0 += av * w[k].x;
            a1 += av * w[k].y;
            a2 += av * w[k].z;
            a3 += av * w[k].w;
        }

        float4 xv = *(const float4*)(xin + (long long)s * HID + 4 * t);
        acc.x += fmaxf(xv.x + a0, 0.f);
        acc.y += fmaxf(xv.y + a1, 0.f);
        acc.z += fmaxf(xv.z + a2, 0.f);
        acc.w += fmaxf(xv.w + a3, 0.f);
    }

    *(float4*)(agg + (long long)node * HID + 4 * t) = acc;   // coalesced row store
}

// ---------------- node phase: out = act(((1+eps)*x + agg) @ W + b) ----------------
// 128 threads: col j = tid&63, slot = tid>>6; 8 nodes per block, 4 per slot (4-way ILP)
template <bool RELU>
__global__ void __launch_bounds__(128) node_kernel(
    const float* __restrict__ xin,
    const float* __restrict__ agg,
    const float* __restrict__ W,     // [64,64]
    const float* __restrict__ b,
    const float* __restrict__ epsp,
    float* __restrict__ out,
    int nN)
{
    __shared__ float srow[8][HID];
    const int j = threadIdx.x & 63;
    const int slot = threadIdx.x >> 6;          // 0..1
    const float scale = 1.f + epsp[0];

    float wc[HID];
    #pragma unroll
    for (int k = 0; k < HID; k++) wc[k] = W[k * HID + j];
    const float bj = b[j];

    int base = blockIdx.x * 8;

    #pragma unroll
    for (int r = 0; r < 4; r++) {
        int n = base + slot * 4 + r;
        if (n < nN)
            srow[slot * 4 + r][j] = scale * xin[(long long)n * HID + j] + agg[(long long)n * HID + j];
    }
    __syncthreads();

    float a0 = bj, a1 = bj, a2 = bj, a3 = bj;
    #pragma unroll
    for (int k = 0; k < HID; k += 4) {
        float4 r0 = *(const float4*)&srow[slot * 4 + 0][k];
        float4 r1 = *(const float4*)&srow[slot * 4 + 1][k];
        float4 r2 = *(const float4*)&srow[slot * 4 + 2][k];
        float4 r3 = *(const float4*)&srow[slot * 4 + 3][k];
        a0 += r0.x * wc[k] + r0.y * wc[k + 1] + r0.z * wc[k + 2] + r0.w * wc[k + 3];
        a1 += r1.x * wc[k] + r1.y * wc[k + 1] + r1.z * wc[k + 2] + r1.w * wc[k + 3];
        a2 += r2.x * wc[k] + r2.y * wc[k + 1] + r2.z * wc[k + 2] + r2.w * wc[k + 3];
        a3 += r3.x * wc[k] + r3.y * wc[k + 1] + r3.z * wc[k + 2] + r3.w * wc[k + 3];
    }

    int n0 = base + slot * 4;
    if (n0 + 0 < nN) out[(long long)(n0 + 0) * HID + j] = RELU ? fmaxf(a0, 0.f) : a0;
    if (n0 + 1 < nN) out[(long long)(n0 + 1) * HID + j] = RELU ? fmaxf(a1, 0.f) : a1;
    if (n0 + 2 < nN) out[(long long)(n0 + 2) * HID + j] = RELU ? fmaxf(a2, 0.f) : a2;
    if (n0 + 3 < nN) out[(long long)(n0 + 3) * HID + j] = RELU ? fmaxf(a3, 0.f) : a3;
}

// ---------------- pooling: scatter-mean over sorted batch ----------------
__global__ void pool_kernel(const float* __restrict__ h,
                            const int* __restrict__ batch,
                            float* __restrict__ pooled,
                            float* __restrict__ cnt,
                            int nN)
{
    const int j = threadIdx.x & 63;
    const int p = threadIdx.x >> 6;
    const int CHUNK = 512;
    int base = blockIdx.x * CHUNK;
    int lim = base + CHUNK;
    if (lim > nN) lim = nN;

    float acc = 0.f;
    float c = 0.f;
    int curg = -1;
    for (int n = base + p; n < lim; n += 4) {
        int g = batch[n];
        if (g != curg) {
            if (curg >= 0) {
                atomicAdd(&pooled[curg * HID + j], acc);
                if (j == 0) atomicAdd(&cnt[curg], c);
            }
            acc = 0.f; c = 0.f; curg = g;
        }
        acc += h[(long long)n * HID + j];
        c += 1.f;
    }
    if (curg >= 0) {
        atomicAdd(&pooled[curg * HID + j], acc);
        if (j == 0) atomicAdd(&cnt[curg], c);
    }
}

// ---------------- head ----------------
__global__ void head_kernel(const float* __restrict__ pooled,
                            const float* __restrict__ cnt,
                            const float* __restrict__ Wm1, const float* __restrict__ bm1,
                            const float* __restrict__ Wm2, const float* __restrict__ bm2,
                            float* __restrict__ out)
{
    int gq = blockIdx.x * blockDim.x + threadIdx.x;
    if (gq >= N_GRAPHS) return;
    float inv = 1.f / fmaxf(cnt[gq], 1.f);
    float row[HID];
    #pragma unroll
    for (int k = 0; k < HID; k++) row[k] = pooled[gq * HID + k] * inv;
    float o[N_TASKS];
    #pragma unroll
    for (int ts = 0; ts < N_TASKS; ts++) o[ts] = bm2[ts];
    for (int jj = 0; jj < HID; jj++) {
        float hv = bm1[jj];
        #pragma unroll 16
        for (int k = 0; k < HID; k++) hv += row[k] * Wm1[k * HID + jj];
        hv = fmaxf(hv, 0.f);
        #pragma unroll
        for (int ts = 0; ts < N_TASKS; ts++) o[ts] += hv * Wm2[jj * N_TASKS + ts];
    }
    #pragma unroll
    for (int ts = 0; ts < N_TASKS; ts++) out[gq * N_TASKS + ts] = o[ts];
}

// ---------------- launch ----------------
extern "C" void kernel_launch(void* const* d_in, const int* in_sizes, int n_in,
                              void* d_out, int out_size) {
    const float* x         = (const float*)d_in[0];
    const int*   eidx      = (const int*)d_in[1];
    const float* edge_attr = (const float*)d_in[2];
    const int*   batch     = (const int*)d_in[3];
    const float* We1 = (const float*)d_in[4];
    const float* be1 = (const float*)d_in[5];
    const float* We2 = (const float*)d_in[6];
    const float* be2 = (const float*)d_in[7];
    const float* W1  = (const float*)d_in[8];
    const float* b1  = (const float*)d_in[9];
    const float* e1  = (const float*)d_in[10];
    const float* W2  = (const float*)d_in[11];
    const float* b2  = (const float*)d_in[12];
    const float* e2  = (const float*)d_in[13];
    const float* W3  = (const float*)d_in[14];
    const float* b3  = (const float*)d_in[15];
    const float* e3  = (const float*)d_in[16];
    const float* Wm1 = (const float*)d_in[17];
    const float* bm1 = (const float*)d_in[18];
    const float* Wm2 = (const float*)d_in[19];
    const float* bm2 = (const float*)d_in[20];
    float* out = (float*)d_out;

    int nN = in_sizes[0] / HID;       // 100000
    int nE = in_sizes[2] / 16;        // 1600000
    const int* src = eidx;
    const int* dst = eidx + nE;

    float *agg, *hA, *hB, *pooled, *cnt, *Wf2, *bf2;
    int *hist, *cur, *offs, *eid_s, *src_s;
    cudaGetSymbolAddress((void**)&agg,    d_agg);
    cudaGetSymbolAddress((void**)&hA,     d_hA);
    cudaGetSymbolAddress((void**)&hB,     d_hB);
    cudaGetSymbolAddress((void**)&pooled, d_pooled);
    cudaGetSymbolAddress((void**)&cnt,    d_cnt);
    cudaGetSymbolAddress((void**)&Wf2,    d_Wf2);
    cudaGetSymbolAddress((void**)&bf2,    d_bf2);
    cudaGetSymbolAddress((void**)&hist,   d_hist);
    cudaGetSymbolAddress((void**)&cur,    d_cur);
    cudaGetSymbolAddress((void**)&offs,   d_offs);
    cudaGetSymbolAddress((void**)&eid_s,  d_eid);
    cudaGetSymbolAddress((void**)&src_s,  d_srcs);

    const int ZB = 256;
    const int eBlocks = (nE + ZB - 1) / ZB;
    const int gatherBlocks = (nN + 7) / 8;
    const int nodeBlocks = (nN + 7) / 8;

    prep_kernel<<<(16 * HID + HID + 127) / 128, 128>>>(We1, be1, We2, be2, Wf2, bf2);

    // ---- CSR build (by dst) ----
    zero_i<<<(nN + ZB - 1) / ZB, ZB>>>(hist, nN);
    zero_i<<<(nN + ZB - 1) / ZB, ZB>>>(cur, nN);
    hist_kernel<<<eBlocks, ZB>>>(dst, hist, nE);
    scan_kernel<<<1, 1024>>>(hist, offs, nN);
    scatter_kernel<<<eBlocks, ZB>>>(src, dst, offs, cur, eid_s, src_s, nE);

    // ---- conv1 ----
    edge_gather_kernel<<<gatherBlocks, 128>>>(x, offs, eid_s, src_s, edge_attr, We1, be1, agg, nN);
    node_kernel<true><<<nodeBlocks, 128>>>(x, agg, W1, b1, e1, hA, nN);

    // ---- conv2 ----
    edge_gather_kernel<<<gatherBlocks, 128>>>(hA, offs, eid_s, src_s, edge_attr, Wf2, bf2, agg, nN);
    node_kernel<true><<<nodeBlocks, 128>>>(hA, agg, W2, b2, e2, hB, nN);

    // ---- conv3 ----
    edge_gather_kernel<<<gatherBlocks, 128>>>(hB, offs, eid_s, src_s, edge_attr, Wf2, bf2, agg, nN);
    node_kernel<false><<<nodeBlocks, 128>>>(hB, agg, W3, b3, e3, hA, nN);

    // ---- pooling + head ----
    zero_f4<<<(N_GRAPHS * HID / 4 + ZB - 1) / ZB, ZB>>>((float4*)pooled, N_GRAPHS * HID / 4);
    zero_f4<<<1, ZB>>>((float4*)cnt, N_GRAPHS / 4);
    pool_kernel<<<(nN + 511) / 512, 256>>>(hA, batch, pooled, cnt, nN);
    head_kernel<<<1, 256>>>(pooled, cnt, Wm1, bm1, Wm2, bm2, out);
}

// round 5
// speedup vs baseline: 1.3317x; 1.2404x over previous
#include <cuda_runtime.h>
#include <cuda_bf16.h>

#define N_NODES_MAX 100000
#define NE_MAX 1600000
#define N_GRAPHS 256
#define HID 64
#define N_TASKS 10
#define EPG 32   // edges per 16-thread group in flat edge kernel

// ---------------- scratch (no allocations allowed) ----------------
__device__ __align__(16) float d_agg[N_NODES_MAX * HID];
__device__ __align__(16) float d_hA[N_NODES_MAX * HID];
__device__ __align__(16) float d_hB[N_NODES_MAX * HID];
__device__ __align__(16) float d_pooled[N_GRAPHS * HID];
__device__ __align__(16) float d_cnt[N_GRAPHS];
__device__ __align__(16) float d_Wf2[16 * HID];
__device__ __align__(16) float d_bf2[HID];
// CSR / sorted-edge scratch
__device__ int d_hist[N_NODES_MAX];
__device__ int d_cur[N_NODES_MAX];
__device__ int d_offs[N_NODES_MAX + 1];
__device__ int d_eid[NE_MAX];
__device__ int d_srcs[NE_MAX];
__device__ int d_dsts[NE_MAX];
__device__ __align__(16) float d_eas[(long long)NE_MAX * 16];  // sorted edge_attr (102 MB)

// ---------------- prep: fused edge weights Wf2 = We1@We2, bf2 = be1@We2 + be2 ----------------
__global__ void prep_kernel(const float* __restrict__ We1, const float* __restrict__ be1,
                            const float* __restrict__ We2, const float* __restrict__ be2,
                            float* __restrict__ Wf2, float* __restrict__ bf2) {
    int idx = blockIdx.x * blockDim.x + threadIdx.x;
    if (idx < 16 * HID) {
        int k = idx >> 6, j = idx & 63;
        float acc = 0.f;
        #pragma unroll 8
        for (int m = 0; m < HID; m++) acc += We1[k * HID + m] * We2[m * HID + j];
        Wf2[idx] = acc;
    } else if (idx < 16 * HID + HID) {
        int j = idx - 16 * HID;
        float acc = be2[j];
        #pragma unroll 8
        for (int m = 0; m < HID; m++) acc += be1[m] * We2[m * HID + j];
        bf2[j] = acc;
    }
}

// ---------------- zero fills ----------------
__global__ void zero_f4(float4* __restrict__ p, int n4) {
    int i = blockIdx.x * blockDim.x + threadIdx.x;
    if (i < n4) p[i] = make_float4(0.f, 0.f, 0.f, 0.f);
}
__global__ void zero_i(int* __restrict__ p, int n) {
    int i = blockIdx.x * blockDim.x + threadIdx.x;
    if (i < n) p[i] = 0;
}

// ---------------- CSR build ----------------
__global__ void hist_kernel(const int* __restrict__ dst, int* __restrict__ hist, int nE) {
    int e = blockIdx.x * blockDim.x + threadIdx.x;
    if (e < nE) atomicAdd(&hist[dst[e]], 1);
}

__global__ void scan_kernel(const int* __restrict__ hist, int* __restrict__ offs, int nN) {
    __shared__ int ssum[1024];
    const int tid = threadIdx.x;
    const int chunk = (nN + 1023) / 1024;
    int begin = tid * chunk;
    int end = begin + chunk; if (end > nN) end = nN;
    if (begin > nN) begin = nN;

    int s = 0;
    for (int i = begin; i < end; i++) s += hist[i];
    ssum[tid] = s;
    __syncthreads();
    for (int off = 1; off < 1024; off <<= 1) {
        int add = (tid >= off) ? ssum[tid - off] : 0;
        __syncthreads();
        ssum[tid] += add;
        __syncthreads();
    }
    int run = (tid == 0) ? 0 : ssum[tid - 1];
    for (int i = begin; i < end; i++) { offs[i] = run; run += hist[i]; }
    if (tid == 1023) offs[nN] = ssum[1023];
}

__global__ void scatter_kernel(const int* __restrict__ src, const int* __restrict__ dst,
                               const int* __restrict__ offs, int* __restrict__ cur,
                               int* __restrict__ eid_s, int* __restrict__ src_s,
                               int* __restrict__ dst_s, int nE) {
    int e = blockIdx.x * blockDim.x + threadIdx.x;
    if (e < nE) {
        int d = dst[e];
        int p = atomicAdd(&cur[d], 1);
        int i = offs[d] + p;
        eid_s[i] = e;
        src_s[i] = src[e];
        dst_s[i] = d;
    }
}

// reorder edge_attr into sorted order: ea_s[i][t] = ea[eid_s[i]][t]
__global__ void __launch_bounds__(256) ea_sort_kernel(
    const int* __restrict__ eid_s, const float* __restrict__ ea,
    float* __restrict__ ea_s, int nE)
{
    int i = blockIdx.x * 16 + (threadIdx.x >> 4);
    int t = threadIdx.x & 15;
    if (i < nE) {
        int eid = eid_s[i];
        ea_s[(long long)i * 16 + t] = __ldg(ea + (long long)eid * 16 + t);
    }
}

// ---------------- flat edge phase: segmented reduction over dst-sorted edges ----------------
// 16 threads per edge-chunk of EPG contiguous sorted edges; thread t owns out cols [4t,4t+4).
// agg must be pre-zeroed.
__global__ void __launch_bounds__(256) edge_flat_kernel(
    const float* __restrict__ xin,
    const float* __restrict__ ea_s,   // [E,16] sorted
    const int* __restrict__ src_s,
    const int* __restrict__ dst_s,
    const float* __restrict__ W,      // [16,64]
    const float* __restrict__ b,      // [64]
    float* __restrict__ agg,
    int nE)
{
    const int tid = threadIdx.x;
    const int t = tid & 15;
    const int g = tid >> 4;                       // 16 groups per block
    const unsigned shfl_base = (tid & 31) & 16;
    const unsigned mask = 0xFFFFu << shfl_base;   // half-warp mask (tail-divergence safe)

    float4 w[16];
    #pragma unroll
    for (int k = 0; k < 16; k++) w[k] = *(const float4*)(W + k * HID + 4 * t);
    const float4 bv = *(const float4*)(b + 4 * t);

    long long base = (long long)(blockIdx.x * 16 + g) * EPG;
    if (base >= nE) return;
    int end = (int)((base + EPG <= nE) ? (base + EPG) : nE);

    int curd = dst_s[base];
    float4 acc = make_float4(0.f, 0.f, 0.f, 0.f);

    #pragma unroll 4
    for (int i = (int)base; i < end; i++) {
        int d = dst_s[i];                          // broadcast across group
        if (d != curd) {
            atomicAdd((float4*)(agg + (long long)curd * HID + 4 * t), acc);
            acc = make_float4(0.f, 0.f, 0.f, 0.f);
            curd = d;
        }
        float eav = ea_s[(long long)i * 16 + t];   // sequential, coalesced 64B/edge
        int s = src_s[i];

        float a0 = bv.x, a1 = bv.y, a2 = bv.z, a3 = bv.w;
        #pragma unroll
        for (int k = 0; k < 16; k++) {
            float av = __shfl_sync(mask, eav, shfl_base + k);
            a0 += av * w[k].x;
            a1 += av * w[k].y;
            a2 += av * w[k].z;
            a3 += av * w[k].w;
        }

        float4 xv = *(const float4*)(xin + (long long)s * HID + 4 * t);  // L2-resident gather
        acc.x += fmaxf(xv.x + a0, 0.f);
        acc.y += fmaxf(xv.y + a1, 0.f);
        acc.z += fmaxf(xv.z + a2, 0.f);
        acc.w += fmaxf(xv.w + a3, 0.f);
    }
    atomicAdd((float4*)(agg + (long long)curd * HID + 4 * t), acc);
}

// ---------------- node phase: out = act(((1+eps)*x + agg) @ W + b) ----------------
template <bool RELU>
__global__ void __launch_bounds__(128) node_kernel(
    const float* __restrict__ xin,
    const float* __restrict__ agg,
    const float* __restrict__ W,     // [64,64]
    const float* __restrict__ b,
    const float* __restrict__ epsp,
    float* __restrict__ out,
    int nN)
{
    __shared__ float srow[8][HID];
    const int j = threadIdx.x & 63;
    const int slot = threadIdx.x >> 6;          // 0..1
    const float scale = 1.f + epsp[0];

    float wc[HID];
    #pragma unroll
    for (int k = 0; k < HID; k++) wc[k] = W[k * HID + j];
    const float bj = b[j];

    int base = blockIdx.x * 8;

    #pragma unroll
    for (int r = 0; r < 4; r++) {
        int n = base + slot * 4 + r;
        if (n < nN)
            srow[slot * 4 + r][j] = scale * xin[(long long)n * HID + j] + agg[(long long)n * HID + j];
    }
    __syncthreads();

    float a0 = bj, a1 = bj, a2 = bj, a3 = bj;
    #pragma unroll
    for (int k = 0; k < HID; k += 4) {
        float4 r0 = *(const float4*)&srow[slot * 4 + 0][k];
        float4 r1 = *(const float4*)&srow[slot * 4 + 1][k];
        float4 r2 = *(const float4*)&srow[slot * 4 + 2][k];
        float4 r3 = *(const float4*)&srow[slot * 4 + 3][k];
        a0 += r0.x * wc[k] + r0.y * wc[k + 1] + r0.z * wc[k + 2] + r0.w * wc[k + 3];
        a1 += r1.x * wc[k] + r1.y * wc[k + 1] + r1.z * wc[k + 2] + r1.w * wc[k + 3];
        a2 += r2.x * wc[k] + r2.y * wc[k + 1] + r2.z * wc[k + 2] + r2.w * wc[k + 3];
        a3 += r3.x * wc[k] + r3.y * wc[k + 1] + r3.z * wc[k + 2] + r3.w * wc[k + 3];
    }

    int n0 = base + slot * 4;
    if (n0 + 0 < nN) out[(long long)(n0 + 0) * HID + j] = RELU ? fmaxf(a0, 0.f) : a0;
    if (n0 + 1 < nN) out[(long long)(n0 + 1) * HID + j] = RELU ? fmaxf(a1, 0.f) : a1;
    if (n0 + 2 < nN) out[(long long)(n0 + 2) * HID + j] = RELU ? fmaxf(a2, 0.f) : a2;
    if (n0 + 3 < nN) out[(long long)(n0 + 3) * HID + j] = RELU ? fmaxf(a3, 0.f) : a3;
}

// ---------------- pooling: scatter-mean over sorted batch ----------------
__global__ void pool_kernel(const float* __restrict__ h,
                            const int* __restrict__ batch,
                            float* __restrict__ pooled,
                            float* __restrict__ cnt,
                            int nN)
{
    const int j = threadIdx.x & 63;
    const int p = threadIdx.x >> 6;
    const int CHUNK = 512;
    int base = blockIdx.x * CHUNK;
    int lim = base + CHUNK;
    if (lim > nN) lim = nN;

    float acc = 0.f;
    float c = 0.f;
    int curg = -1;
    for (int n = base + p; n < lim; n += 4) {
        int g = batch[n];
        if (g != curg) {
            if (curg >= 0) {
                atomicAdd(&pooled[curg * HID + j], acc);
                if (j == 0) atomicAdd(&cnt[curg], c);
            }
            acc = 0.f; c = 0.f; curg = g;
        }
        acc += h[(long long)n * HID + j];
        c += 1.f;
    }
    if (curg >= 0) {
        atomicAdd(&pooled[curg * HID + j], acc);
        if (j == 0) atomicAdd(&cnt[curg], c);
    }
}

// ---------------- head ----------------
__global__ void head_kernel(const float* __restrict__ pooled,
                            const float* __restrict__ cnt,
                            const float* __restrict__ Wm1, const float* __restrict__ bm1,
                            const float* __restrict__ Wm2, const float* __restrict__ bm2,
                            float* __restrict__ out)
{
    int gq = blockIdx.x * blockDim.x + threadIdx.x;
    if (gq >= N_GRAPHS) return;
    float inv = 1.f / fmaxf(cnt[gq], 1.f);
    float row[HID];
    #pragma unroll
    for (int k = 0; k < HID; k++) row[k] = pooled[gq * HID + k] * inv;
    float o[N_TASKS];
    #pragma unroll
    for (int ts = 0; ts < N_TASKS; ts++) o[ts] = bm2[ts];
    for (int jj = 0; jj < HID; jj++) {
        float hv = bm1[jj];
        #pragma unroll 16
        for (int k = 0; k < HID; k++) hv += row[k] * Wm1[k * HID + jj];
        hv = fmaxf(hv, 0.f);
        #pragma unroll
        for (int ts = 0; ts < N_TASKS; ts++) o[ts] += hv * Wm2[jj * N_TASKS + ts];
    }
    #pragma unroll
    for (int ts = 0; ts < N_TASKS; ts++) out[gq * N_TASKS + ts] = o[ts];
}

// ---------------- launch ----------------
extern "C" void kernel_launch(void* const* d_in, const int* in_sizes, int n_in,
                              void* d_out, int out_size) {
    const float* x         = (const float*)d_in[0];
    const int*   eidx      = (const int*)d_in[1];
    const float* edge_attr = (const float*)d_in[2];
    const int*   batch     = (const int*)d_in[3];
    const float* We1 = (const float*)d_in[4];
    const float* be1 = (const float*)d_in[5];
    const float* We2 = (const float*)d_in[6];
    const float* be2 = (const float*)d_in[7];
    const float* W1  = (const float*)d_in[8];
    const float* b1  = (const float*)d_in[9];
    const float* e1  = (const float*)d_in[10];
    const float* W2  = (const float*)d_in[11];
    const float* b2  = (const float*)d_in[12];
    const float* e2  = (const float*)d_in[13];
    const float* W3  = (const float*)d_in[14];
    const float* b3  = (const float*)d_in[15];
    const float* e3  = (const float*)d_in[16];
    const float* Wm1 = (const float*)d_in[17];
    const float* bm1 = (const float*)d_in[18];
    const float* Wm2 = (const float*)d_in[19];
    const float* bm2 = (const float*)d_in[20];
    float* out = (float*)d_out;

    int nN = in_sizes[0] / HID;       // 100000
    int nE = in_sizes[2] / 16;        // 1600000
    const int* src = eidx;
    const int* dst = eidx + nE;

    float *agg, *hA, *hB, *pooled, *cnt, *Wf2, *bf2, *ea_s;
    int *hist, *cur, *offs, *eid_s, *src_s, *dst_s;
    cudaGetSymbolAddress((void**)&agg,    d_agg);
    cudaGetSymbolAddress((void**)&hA,     d_hA);
    cudaGetSymbolAddress((void**)&hB,     d_hB);
    cudaGetSymbolAddress((void**)&pooled, d_pooled);
    cudaGetSymbolAddress((void**)&cnt,    d_cnt);
    cudaGetSymbolAddress((void**)&Wf2,    d_Wf2);
    cudaGetSymbolAddress((void**)&bf2,    d_bf2);
    cudaGetSymbolAddress((void**)&hist,   d_hist);
    cudaGetSymbolAddress((void**)&cur,    d_cur);
    cudaGetSymbolAddress((void**)&offs,   d_offs);
    cudaGetSymbolAddress((void**)&eid_s,  d_eid);
    cudaGetSymbolAddress((void**)&src_s,  d_srcs);
    cudaGetSymbolAddress((void**)&dst_s,  d_dsts);
    cudaGetSymbolAddress((void**)&ea_s,   d_eas);

    const int ZB = 256;
    const int eBlocks = (nE + ZB - 1) / ZB;
    const int nodeBlocks = (nN + 7) / 8;
    const int nodeF4 = nN * HID / 4;
    const int flatBlocks = (nE + 16 * EPG - 1) / (16 * EPG);

    prep_kernel<<<(16 * HID + HID + 127) / 128, 128>>>(We1, be1, We2, be2, Wf2, bf2);

    // ---- sort edges by dst (CSR) + reorder edge_attr (one-time) ----
    zero_i<<<(nN + ZB - 1) / ZB, ZB>>>(hist, nN);
    zero_i<<<(nN + ZB - 1) / ZB, ZB>>>(cur, nN);
    hist_kernel<<<eBlocks, ZB>>>(dst, hist, nE);
    scan_kernel<<<1, 1024>>>(hist, offs, nN);
    scatter_kernel<<<eBlocks, ZB>>>(src, dst, offs, cur, eid_s, src_s, dst_s, nE);
    ea_sort_kernel<<<(nE + 15) / 16, 256>>>(eid_s, edge_attr, ea_s, nE);

    // ---- conv1 ----
    zero_f4<<<(nodeF4 + ZB - 1) / ZB, ZB>>>((float4*)agg, nodeF4);
    edge_flat_kernel<<<flatBlocks, 256>>>(x, ea_s, src_s, dst_s, We1, be1, agg, nE);
    node_kernel<true><<<nodeBlocks, 128>>>(x, agg, W1, b1, e1, hA, nN);

    // ---- conv2 ----
    zero_f4<<<(nodeF4 + ZB - 1) / ZB, ZB>>>((float4*)agg, nodeF4);
    edge_flat_kernel<<<flatBlocks, 256>>>(hA, ea_s, src_s, dst_s, Wf2, bf2, agg, nE);
    node_kernel<true><<<nodeBlocks, 128>>>(hA, agg, W2, b2, e2, hB, nN);

    // ---- conv3 ----
    zero_f4<<<(nodeF4 + ZB - 1) / ZB, ZB>>>((float4*)agg, nodeF4);
    edge_flat_kernel<<<flatBlocks, 256>>>(hB, ea_s, src_s, dst_s, Wf2, bf2, agg, nE);
    node_kernel<false><<<nodeBlocks, 128>>>(hB, agg, W3, b3, e3, hA, nN);

    // ---- pooling + head ----
    zero_f4<<<(N_GRAPHS * HID / 4 + ZB - 1) / ZB, ZB>>>((float4*)pooled, N_GRAPHS * HID / 4);
    zero_f4<<<1, ZB>>>((float4*)cnt, N_GRAPHS / 4);
    pool_kernel<<<(nN + 511) / 512, 256>>>(hA, batch, pooled, cnt, nN);
    head_kernel<<<1, 256>>>(pooled, cnt, Wm1, bm1, Wm2, bm2, out);
}